// round 14
// baseline (speedup 1.0000x reference)
#include <cuda_runtime.h>
#include <cuda_fp16.h>
#include <cstdint>

// Problem constants (fixed by the dataset)
#define N0C 10000
#define N1C 40000
#define N2C 160000
#define E1C 240000
#define E2C 960000
#define NKEYS (N1C + N2C)          // 200000 (concatenated src-key domain)
#define NEDGE (E1C + E2C)          // 1200000
#define NB1 ((NKEYS + 4095) / 4096) // 49 scan blocks

// Static scratch (no allocation allowed)
__device__ __half g_Z[N2C * 9 * 16];               // 46.1 MB (>= N1C*9*32 halves)
__device__ float g_bufA[N2C * 32];                 // 20.5 MB
__device__ float g_bufB[N2C * 32];                 // 20.5 MB
__device__ unsigned int g_Bp[19200];               // packed B fragments
__device__ int g_offs[NKEYS];
__device__ int g_bsum[64];
__device__ int g_srcP[NEDGE];
__device__ int g_dstP[NEDGE];
__device__ float2 g_psP[NEDGE];

#define BP_1A 0
#define BP_2A 10240
#define BP_1B 15360
#define BP_2B 17920

// ===========================================================================
// Pack B fragments (mma.m16n8k16 fragment order)
// ===========================================================================
__device__ __forceinline__ float wt_val(const float* __restrict__ W,
                                        const float* __restrict__ R,
                                        int CIN, int COUT, int j, int k) {
    if (j < 9 * COUT) {
        int kk = j / COUT;
        int co = j - kk * COUT;
        return W[((size_t)kk * CIN + k) * COUT + co];
    }
    return R[(size_t)k * COUT + (j - 9 * COUT)];
}

__device__ __forceinline__ void pack_b_one(const float* __restrict__ W,
                                           const float* __restrict__ R,
                                           int CIN, int COUT,
                                           unsigned int* __restrict__ Bp, int u) {
    int r = u & 1;
    int lane = (u >> 1) & 31;
    int rest = u >> 6;
    int KS = CIN / 16;
    int ks = rest % KS;
    int nt = rest / KS;
    int j = nt * 8 + (lane >> 2);
    int kb = ks * 16 + (lane & 3) * 2 + r * 8;
    __half2 h = __floats2half2_rn(wt_val(W, R, CIN, COUT, j, kb),
                                  wt_val(W, R, CIN, COUT, j, kb + 1));
    Bp[u] = *reinterpret_cast<unsigned int*>(&h);
}

__global__ void pack_all_kernel(const float* W1a, const float* R1a,
                                const float* W2a, const float* R2a,
                                const float* W1b, const float* R1b,
                                const float* W2b, const float* R2b,
                                unsigned int* __restrict__ Bp) {
    int i = blockIdx.x * blockDim.x + threadIdx.x;
    if (i < 10240)       pack_b_one(W1a, R1a, 64, 32, Bp + BP_1A, i);
    else if (i < 15360)  pack_b_one(W2a, R2a, 32, 32, Bp + BP_2A, i - 10240);
    else if (i < 17920)  pack_b_one(W1b, R1b, 32, 16, Bp + BP_1B, i - 15360);
    else if (i < 19200)  pack_b_one(W2b, R2b, 16, 16, Bp + BP_2B, i - 17920);
}

// ===========================================================================
// Counting sort of ALL edges (both levels) by src key.
// ===========================================================================
__global__ void zero_kernel(int* __restrict__ p, int n) {
    int i = blockIdx.x * blockDim.x + threadIdx.x;
    if (i < n) p[i] = 0;
}

__global__ void hist_kernel(const int* __restrict__ e1src,
                            const int* __restrict__ e2src,
                            int* __restrict__ cnt) {
    int i = blockIdx.x * blockDim.x + threadIdx.x;
    if (i >= NEDGE) return;
    int key = (i < E1C) ? __ldg(e1src + i) : (N1C + __ldg(e2src + (i - E1C)));
    atomicAdd(&cnt[key], 1);
}

// Block scan: 1024 threads x 4 elems = 4096/block; warp-shuffle based.
__global__ void scan1_kernel(int* __restrict__ offs, int* __restrict__ bsum) {
    __shared__ int wsum[32];
    int t = threadIdx.x;
    int lane = t & 31;
    int w = t >> 5;
    int base = blockIdx.x * 4096 + t * 4;
    int c0 = (base + 0 < NKEYS) ? offs[base + 0] : 0;
    int c1 = (base + 1 < NKEYS) ? offs[base + 1] : 0;
    int c2 = (base + 2 < NKEYS) ? offs[base + 2] : 0;
    int c3 = (base + 3 < NKEYS) ? offs[base + 3] : 0;
    int s = c0 + c1 + c2 + c3;
    // warp inclusive scan of s
    int v = s;
#pragma unroll
    for (int off = 1; off < 32; off <<= 1) {
        int u = __shfl_up_sync(0xFFFFFFFFu, v, off);
        if (lane >= off) v += u;
    }
    if (lane == 31) wsum[w] = v;
    __syncthreads();
    if (w == 0) {
        int x = wsum[lane];
        int y = x;
#pragma unroll
        for (int off = 1; off < 32; off <<= 1) {
            int u = __shfl_up_sync(0xFFFFFFFFu, y, off);
            if (lane >= off) y += u;
        }
        wsum[lane] = y - x;     // exclusive warp offsets
    }
    __syncthreads();
    int incl = v + wsum[w];     // inclusive over block
    int excl = incl - s;
    if (t == 1023) bsum[blockIdx.x] = incl;
    if (base + 0 < NKEYS) offs[base + 0] = excl;
    if (base + 1 < NKEYS) offs[base + 1] = excl + c0;
    if (base + 2 < NKEYS) offs[base + 2] = excl + c0 + c1;
    if (base + 3 < NKEYS) offs[base + 3] = excl + c0 + c1 + c2;
}

__global__ void scan2_kernel(int* __restrict__ bsum) {
    int t = threadIdx.x;       // 64 threads, NB1 <= 64
    int v = (t < NB1) ? bsum[t] : 0;
    __shared__ int sh[64];
    sh[t] = v;
    __syncthreads();
    for (int off = 1; off < 64; off <<= 1) {
        int u = (t >= off) ? sh[t - off] : 0;
        __syncthreads();
        sh[t] += u;
        __syncthreads();
    }
    if (t < NB1) bsum[t] = sh[t] - v;   // exclusive
}

// Scatter with scan3 folded in: global pos = local-scan + block offset.
__global__ void scatter_kernel(const int* __restrict__ e1src, const int* __restrict__ e1dst,
                               const float* __restrict__ ps1,
                               const int* __restrict__ e2src, const int* __restrict__ e2dst,
                               const float* __restrict__ ps2,
                               int* __restrict__ offs, const int* __restrict__ bsum,
                               int* __restrict__ srcP, int* __restrict__ dstP,
                               float2* __restrict__ psP) {
    int i = blockIdx.x * blockDim.x + threadIdx.x;
    if (i >= NEDGE) return;
    int s, d, key; float2 ps;
    if (i < E1C) {
        s = __ldg(e1src + i); d = __ldg(e1dst + i);
        ps = __ldg(reinterpret_cast<const float2*>(ps1) + i);
        key = s;
    } else {
        int j = i - E1C;
        s = __ldg(e2src + j); d = __ldg(e2dst + j);
        ps = __ldg(reinterpret_cast<const float2*>(ps2) + j);
        key = N1C + s;
    }
    int pos = atomicAdd(&offs[key], 1) + __ldg(&bsum[key >> 12]);
    srcP[pos] = s; dstP[pos] = d; psP[pos] = ps;
}

// ===========================================================================
// Warp-autonomous HMMA node kernel (R8 shape): NO smem, NO barriers.
// launch_bounds(256, 4) -> <=64 regs, 4 blocks/SM.
// ===========================================================================
template <int CIN, int COUT>
__device__ __forceinline__ unsigned int ldcvt(const float* __restrict__ xA, int CA,
                                              const float* __restrict__ xB,
                                              int reluA, int r, int c) {
    float2 v;
    if (c < CA) {
        v = __ldg(reinterpret_cast<const float2*>(xA + (size_t)r * CA + c));
        if (reluA) { v.x = fmaxf(v.x, 0.f); v.y = fmaxf(v.y, 0.f); }
    } else {
        v = __ldg(reinterpret_cast<const float2*>(xB + (size_t)r * (CIN - CA) + (c - CA)));
    }
    __half2 h = __floats2half2_rn(v.x, v.y);
    return *reinterpret_cast<unsigned int*>(&h);
}

template <int CIN, int COUT>
__global__ void __launch_bounds__(256, 4)
node_mma_kernel(const float* __restrict__ xA, int CA,
                const float* __restrict__ xB,
                const int* __restrict__ gidx, int reluA,
                const unsigned int* __restrict__ Bp,
                const float* __restrict__ bias,
                __half* __restrict__ Z, float* __restrict__ O) {
    constexpr int KS = CIN / 16;
    constexpr int NT_TOT = 10 * COUT / 8;
    constexpr int NTW = NT_TOT / 4;
    constexpr int ZW = 9 * COUT;

    int tid = threadIdx.x;
    int lane = tid & 31;
    int wid = tid >> 5;
    int mg = wid >> 2;
    int ng = wid & 3;
    int g = lane >> 2;
    int tig = lane & 3;
    int nodeBase = blockIdx.x * 32;

    int n0 = nodeBase + mg * 16 + g;
    int n1 = n0 + 8;
    int r0 = gidx ? __ldg(gidx + n0) : n0;
    int r1 = gidx ? __ldg(gidx + n1) : n1;

    float acc[NTW][4];
#pragma unroll
    for (int t = 0; t < NTW; t++)
#pragma unroll
        for (int q = 0; q < 4; q++) acc[t][q] = 0.f;

#pragma unroll
    for (int ks = 0; ks < KS; ks++) {
        int cb = ks * 16 + tig * 2;
        unsigned int a0 = ldcvt<CIN, COUT>(xA, CA, xB, reluA, r0, cb);
        unsigned int a1 = ldcvt<CIN, COUT>(xA, CA, xB, reluA, r1, cb);
        unsigned int a2 = ldcvt<CIN, COUT>(xA, CA, xB, reluA, r0, cb + 8);
        unsigned int a3 = ldcvt<CIN, COUT>(xA, CA, xB, reluA, r1, cb + 8);
#pragma unroll
        for (int nt = 0; nt < NTW; nt++) {
            int gnt = ng * NTW + nt;
            uint2 bb = __ldg(reinterpret_cast<const uint2*>(
                &Bp[((gnt * KS + ks) * 32 + lane) * 2]));
            asm volatile(
                "mma.sync.aligned.m16n8k16.row.col.f32.f16.f16.f32 "
                "{%0,%1,%2,%3}, {%4,%5,%6,%7}, {%8,%9}, {%0,%1,%2,%3};"
                : "+f"(acc[nt][0]), "+f"(acc[nt][1]),
                  "+f"(acc[nt][2]), "+f"(acc[nt][3])
                : "r"(a0), "r"(a1), "r"(a2), "r"(a3), "r"(bb.x), "r"(bb.y));
        }
    }

#pragma unroll
    for (int nt = 0; nt < NTW; nt++) {
        int gnt = ng * NTW + nt;
        int jbase = gnt * 8 + tig * 2;
        if (gnt * 8 < ZW) {
            __half2 h0 = __floats2half2_rn(acc[nt][0], acc[nt][1]);
            __half2 h1 = __floats2half2_rn(acc[nt][2], acc[nt][3]);
            *reinterpret_cast<__half2*>(Z + (size_t)n0 * ZW + jbase) = h0;
            *reinterpret_cast<__half2*>(Z + (size_t)n1 * ZW + jbase) = h1;
        } else {
            int co = jbase - ZW;
            float bx = __ldg(bias + co), by = __ldg(bias + co + 1);
            float2 w0 = make_float2(acc[nt][0] + bx, acc[nt][1] + by);
            float2 w1 = make_float2(acc[nt][2] + bx, acc[nt][3] + by);
            *reinterpret_cast<float2*>(O + (size_t)n0 * COUT + co) = w0;
            *reinterpret_cast<float2*>(O + (size_t)n1 * COUT + co) = w1;
        }
    }
}

// ---------------------------------------------------------------------------
// Edge kernel (R8 shape, 8 ch/thread) on src-sorted permuted edge arrays.
// ---------------------------------------------------------------------------
template <int COUT>
__global__ void edge_kernel(const int* __restrict__ src,
                            const int* __restrict__ dst,
                            const float2* __restrict__ ps,
                            const __half* __restrict__ Z,
                            float* __restrict__ O, int E) {
    constexpr int TPE = COUT / 8;
    int tid = blockIdx.x * blockDim.x + threadIdx.x;
    int e = tid / TPE;
    int g = tid - e * TPE;
    if (e >= E) return;

    float2 p = __ldg(ps + e);
    float t0 = p.x, t1 = p.y;
    float a0 = 0.5f * (1.f - t0) * (1.f - t0);
    float a1 = -t0 * t0 + t0 + 0.5f;
    float a2 = 0.5f * t0 * t0;
    float c0 = 0.5f * (1.f - t1) * (1.f - t1);
    float c1 = -t1 * t1 + t1 + 0.5f;
    float c2 = 0.5f * t1 * t1;
    float b[9] = {a0 * c0, a0 * c1, a0 * c2,
                  a1 * c0, a1 * c1, a1 * c2,
                  a2 * c0, a2 * c1, a2 * c2};

    int s = __ldg(src + e);
    int d = __ldg(dst + e);
    const __half* zb = Z + (size_t)s * (9 * COUT) + g * 8;
    float4 acc0 = make_float4(0.f, 0.f, 0.f, 0.f);
    float4 acc1 = make_float4(0.f, 0.f, 0.f, 0.f);
#pragma unroll
    for (int k = 0; k < 9; k++) {
        float bk = b[k];
        uint4 raw = __ldg(reinterpret_cast<const uint4*>(zb + k * COUT));
        float2 f0 = __half22float2(*reinterpret_cast<const __half2*>(&raw.x));
        float2 f1 = __half22float2(*reinterpret_cast<const __half2*>(&raw.y));
        float2 f2 = __half22float2(*reinterpret_cast<const __half2*>(&raw.z));
        float2 f3 = __half22float2(*reinterpret_cast<const __half2*>(&raw.w));
        acc0.x = fmaf(bk, f0.x, acc0.x);
        acc0.y = fmaf(bk, f0.y, acc0.y);
        acc0.z = fmaf(bk, f1.x, acc0.z);
        acc0.w = fmaf(bk, f1.y, acc0.w);
        acc1.x = fmaf(bk, f2.x, acc1.x);
        acc1.y = fmaf(bk, f2.y, acc1.y);
        acc1.z = fmaf(bk, f3.x, acc1.z);
        acc1.w = fmaf(bk, f3.y, acc1.w);
    }
    float* o = O + (size_t)d * COUT + g * 8;
    asm volatile("red.global.add.v4.f32 [%0], {%1, %2, %3, %4};"
                 :: "l"(o), "f"(acc0.x), "f"(acc0.y), "f"(acc0.z), "f"(acc0.w)
                 : "memory");
    asm volatile("red.global.add.v4.f32 [%0], {%1, %2, %3, %4};"
                 :: "l"(o + 4), "f"(acc1.x), "f"(acc1.y), "f"(acc1.z), "f"(acc1.w)
                 : "memory");
}

__global__ void relu_copy4_kernel(const float4* __restrict__ in,
                                  float4* __restrict__ out, int n4) {
    int i = blockIdx.x * blockDim.x + threadIdx.x;
    if (i >= n4) return;
    float4 v = in[i];
    v.x = fmaxf(v.x, 0.f); v.y = fmaxf(v.y, 0.f);
    v.z = fmaxf(v.z, 0.f); v.w = fmaxf(v.w, 0.f);
    out[i] = v;
}

// ---------------------------------------------------------------------------
extern "C" void kernel_launch(void* const* d_in, const int* in_sizes, int n_in,
                              void* d_out, int out_size) {
    const float* x0      = (const float*)d_in[0];
    const int*   unpool1 = (const int*)d_in[1];
    const int*   edge1   = (const int*)d_in[2];
    const float* pseudo1 = (const float*)d_in[3];
    const float* skip1   = (const float*)d_in[4];
    const int*   unpool2 = (const int*)d_in[5];
    const int*   edge2   = (const int*)d_in[6];
    const float* pseudo2 = (const float*)d_in[7];
    const float* skip2   = (const float*)d_in[8];
    const float* W1a = (const float*)d_in[9];
    const float* R1a = (const float*)d_in[10];
    const float* b1a = (const float*)d_in[11];
    const float* W2a = (const float*)d_in[12];
    const float* R2a = (const float*)d_in[13];
    const float* b2a = (const float*)d_in[14];
    const float* W1b = (const float*)d_in[15];
    const float* R1b = (const float*)d_in[16];
    const float* b1b = (const float*)d_in[17];
    const float* W2b = (const float*)d_in[18];
    const float* R2b = (const float*)d_in[19];
    const float* b2b = (const float*)d_in[20];

    __half* ZP;
    float *bufA, *bufB;
    unsigned int* Bp;
    int *offs, *bsum, *srcP, *dstP;
    float2* psP;
    cudaGetSymbolAddress((void**)&ZP, g_Z);
    cudaGetSymbolAddress((void**)&bufA, g_bufA);
    cudaGetSymbolAddress((void**)&bufB, g_bufB);
    cudaGetSymbolAddress((void**)&Bp, g_Bp);
    cudaGetSymbolAddress((void**)&offs, g_offs);
    cudaGetSymbolAddress((void**)&bsum, g_bsum);
    cudaGetSymbolAddress((void**)&srcP, g_srcP);
    cudaGetSymbolAddress((void**)&dstP, g_dstP);
    cudaGetSymbolAddress((void**)&psP, g_psP);

    const int N1 = N1C, N2 = N2C, E1 = E1C, E2 = E2C;

    // ---- pack B fragments ----
    pack_all_kernel<<<(19200 + 255) / 256, 256>>>(W1a, R1a, W2a, R2a,
                                                  W1b, R1b, W2b, R2b, Bp);

    // ---- counting sort of all edges by src (both levels together) ----
    zero_kernel<<<(NKEYS + 255) / 256, 256>>>(offs, NKEYS);
    hist_kernel<<<(NEDGE + 255) / 256, 256>>>(edge1, edge2, offs);
    scan1_kernel<<<NB1, 1024>>>(offs, bsum);
    scan2_kernel<<<1, 64>>>(bsum);
    scatter_kernel<<<(NEDGE + 255) / 256, 256>>>(edge1, edge1 + E1, pseudo1,
                                                 edge2, edge2 + E2, pseudo2,
                                                 offs, bsum, srcP, dstP, psP);

    // ===================== Level 1: 64 -> 32 (N1, E1) =====================
    node_mma_kernel<64, 32><<<N1 / 32, 256>>>(x0, 64, nullptr, unpool1, 0,
                                              Bp + BP_1A, b1a, ZP, bufA);
    edge_kernel<32><<<(E1 * 4 + 255) / 256, 256>>>(srcP, dstP, psP, ZP, bufA, E1);

    node_mma_kernel<64, 32><<<N1 / 32, 256>>>(bufA, 32, skip1, nullptr, 1,
                                              Bp + BP_1A, b1a, ZP, bufB);
    edge_kernel<32><<<(E1 * 4 + 255) / 256, 256>>>(srcP, dstP, psP, ZP, bufB, E1);

    node_mma_kernel<32, 32><<<N1 / 32, 256>>>(bufB, 32, nullptr, nullptr, 1,
                                              Bp + BP_2A, b2a, ZP, bufA);
    edge_kernel<32><<<(E1 * 4 + 255) / 256, 256>>>(srcP, dstP, psP, ZP, bufA, E1);
    // bufA = h1 (pre-relu; relu applied at gather below)

    // ===================== Level 2: 32 -> 16 (N2, E2) =====================
    node_mma_kernel<32, 16><<<N2 / 32, 256>>>(bufA, 32, nullptr, unpool2, 1,
                                              Bp + BP_1B, b1b, ZP, bufB);
    edge_kernel<16><<<(E2 * 2 + 255) / 256, 256>>>(srcP + E1, dstP + E1, psP + E1, ZP, bufB, E2);

    node_mma_kernel<32, 16><<<N2 / 32, 256>>>(bufB, 16, skip2, nullptr, 1,
                                              Bp + BP_1B, b1b, ZP, bufA);
    edge_kernel<16><<<(E2 * 2 + 255) / 256, 256>>>(srcP + E1, dstP + E1, psP + E1, ZP, bufA, E2);

    node_mma_kernel<16, 16><<<N2 / 32, 256>>>(bufA, 16, nullptr, nullptr, 1,
                                              Bp + BP_2B, b2b, ZP, bufB);
    edge_kernel<16><<<(E2 * 2 + 255) / 256, 256>>>(srcP + E1, dstP + E1, psP + E1, ZP, bufB, E2);

    // final relu -> output
    int n4 = N2 * 16 / 4;
    relu_copy4_kernel<<<(n4 + 255) / 256, 256>>>((const float4*)bufB,
                                                 (float4*)d_out, n4);
}

// round 15
// speedup vs baseline: 1.0436x; 1.0436x over previous
#include <cuda_runtime.h>
#include <cuda_fp16.h>
#include <cstdint>

// Problem constants (fixed by the dataset)
#define N0C 10000
#define N1C 40000
#define N2C 160000
#define E1C 240000
#define E2C 960000
#define NKEYS (N1C + N2C)          // 200000 (concatenated src-key domain)
#define NEDGE (E1C + E2C)          // 1200000
#define NB1 ((NKEYS + 4095) / 4096) // 49 scan blocks

// Static scratch (no allocation allowed)
__device__ __half g_Z[N2C * 9 * 16];               // 46.1 MB (>= N1C*9*32 halves)
__device__ float g_bufA[N2C * 32];                 // 20.5 MB
__device__ float g_bufB[N2C * 32];                 // 20.5 MB
__device__ unsigned int g_Bp[19200];               // packed B fragments
__device__ int g_offs[NKEYS];
__device__ int g_bsum[64];
__device__ int g_srcP[NEDGE];
__device__ int g_dstP[NEDGE];
__device__ float2 g_psP[NEDGE];

#define BP_1A 0
#define BP_2A 10240
#define BP_1B 15360
#define BP_2B 17920

// ===========================================================================
// Pack B fragments (mma.m16n8k16 fragment order)
// ===========================================================================
__device__ __forceinline__ float wt_val(const float* __restrict__ W,
                                        const float* __restrict__ R,
                                        int CIN, int COUT, int j, int k) {
    if (j < 9 * COUT) {
        int kk = j / COUT;
        int co = j - kk * COUT;
        return W[((size_t)kk * CIN + k) * COUT + co];
    }
    return R[(size_t)k * COUT + (j - 9 * COUT)];
}

__device__ __forceinline__ void pack_b_one(const float* __restrict__ W,
                                           const float* __restrict__ R,
                                           int CIN, int COUT,
                                           unsigned int* __restrict__ Bp, int u) {
    int r = u & 1;
    int lane = (u >> 1) & 31;
    int rest = u >> 6;
    int KS = CIN / 16;
    int ks = rest % KS;
    int nt = rest / KS;
    int j = nt * 8 + (lane >> 2);
    int kb = ks * 16 + (lane & 3) * 2 + r * 8;
    __half2 h = __floats2half2_rn(wt_val(W, R, CIN, COUT, j, kb),
                                  wt_val(W, R, CIN, COUT, j, kb + 1));
    Bp[u] = *reinterpret_cast<unsigned int*>(&h);
}

__global__ void pack_all_kernel(const float* W1a, const float* R1a,
                                const float* W2a, const float* R2a,
                                const float* W1b, const float* R1b,
                                const float* W2b, const float* R2b,
                                unsigned int* __restrict__ Bp) {
    int i = blockIdx.x * blockDim.x + threadIdx.x;
    if (i < 10240)       pack_b_one(W1a, R1a, 64, 32, Bp + BP_1A, i);
    else if (i < 15360)  pack_b_one(W2a, R2a, 32, 32, Bp + BP_2A, i - 10240);
    else if (i < 17920)  pack_b_one(W1b, R1b, 32, 16, Bp + BP_1B, i - 15360);
    else if (i < 19200)  pack_b_one(W2b, R2b, 16, 16, Bp + BP_2B, i - 17920);
}

// ===========================================================================
// Counting sort of ALL edges (both levels) by src key.
// ===========================================================================
__global__ void zero_kernel(int* __restrict__ p, int n) {
    int i = blockIdx.x * blockDim.x + threadIdx.x;
    if (i < n) p[i] = 0;
}

__global__ void hist_kernel(const int* __restrict__ e1src,
                            const int* __restrict__ e2src,
                            int* __restrict__ cnt) {
    int i = blockIdx.x * blockDim.x + threadIdx.x;
    if (i >= NEDGE) return;
    int key = (i < E1C) ? __ldg(e1src + i) : (N1C + __ldg(e2src + (i - E1C)));
    atomicAdd(&cnt[key], 1);
}

// Block scan: 1024 threads x 4 elems = 4096/block; warp-shuffle based.
__global__ void scan1_kernel(int* __restrict__ offs, int* __restrict__ bsum) {
    __shared__ int wsum[32];
    int t = threadIdx.x;
    int lane = t & 31;
    int w = t >> 5;
    int base = blockIdx.x * 4096 + t * 4;
    int c0 = (base + 0 < NKEYS) ? offs[base + 0] : 0;
    int c1 = (base + 1 < NKEYS) ? offs[base + 1] : 0;
    int c2 = (base + 2 < NKEYS) ? offs[base + 2] : 0;
    int c3 = (base + 3 < NKEYS) ? offs[base + 3] : 0;
    int s = c0 + c1 + c2 + c3;
    int v = s;
#pragma unroll
    for (int off = 1; off < 32; off <<= 1) {
        int u = __shfl_up_sync(0xFFFFFFFFu, v, off);
        if (lane >= off) v += u;
    }
    if (lane == 31) wsum[w] = v;
    __syncthreads();
    if (w == 0) {
        int x = wsum[lane];
        int y = x;
#pragma unroll
        for (int off = 1; off < 32; off <<= 1) {
            int u = __shfl_up_sync(0xFFFFFFFFu, y, off);
            if (lane >= off) y += u;
        }
        wsum[lane] = y - x;     // exclusive warp offsets
    }
    __syncthreads();
    int incl = v + wsum[w];     // inclusive over block
    int excl = incl - s;
    if (t == 1023) bsum[blockIdx.x] = incl;
    if (base + 0 < NKEYS) offs[base + 0] = excl;
    if (base + 1 < NKEYS) offs[base + 1] = excl + c0;
    if (base + 2 < NKEYS) offs[base + 2] = excl + c0 + c1;
    if (base + 3 < NKEYS) offs[base + 3] = excl + c0 + c1 + c2;
}

__global__ void scan2_kernel(int* __restrict__ bsum) {
    int t = threadIdx.x;       // 64 threads, NB1 <= 64
    int v = (t < NB1) ? bsum[t] : 0;
    __shared__ int sh[64];
    sh[t] = v;
    __syncthreads();
    for (int off = 1; off < 64; off <<= 1) {
        int u = (t >= off) ? sh[t - off] : 0;
        __syncthreads();
        sh[t] += u;
        __syncthreads();
    }
    if (t < NB1) bsum[t] = sh[t] - v;   // exclusive
}

// Scatter with block-offset add folded in: pos = local-scan + bsum[blk].
__global__ void scatter_kernel(const int* __restrict__ e1src, const int* __restrict__ e1dst,
                               const float* __restrict__ ps1,
                               const int* __restrict__ e2src, const int* __restrict__ e2dst,
                               const float* __restrict__ ps2,
                               int* __restrict__ offs, const int* __restrict__ bsum,
                               int* __restrict__ srcP, int* __restrict__ dstP,
                               float2* __restrict__ psP) {
    int i = blockIdx.x * blockDim.x + threadIdx.x;
    if (i >= NEDGE) return;
    int s, d, key; float2 ps;
    if (i < E1C) {
        s = __ldg(e1src + i); d = __ldg(e1dst + i);
        ps = __ldg(reinterpret_cast<const float2*>(ps1) + i);
        key = s;
    } else {
        int j = i - E1C;
        s = __ldg(e2src + j); d = __ldg(e2dst + j);
        ps = __ldg(reinterpret_cast<const float2*>(ps2) + j);
        key = N1C + s;
    }
    int pos = atomicAdd(&offs[key], 1) + __ldg(&bsum[key >> 12]);
    srcP[pos] = s; dstP[pos] = d; psP[pos] = ps;
}

// ===========================================================================
// Warp-autonomous HMMA node kernel (R8/R13 shape): NO smem, NO barriers,
// plain launch_bounds(256) -> natural 80 regs, 3 blocks/SM.
// ===========================================================================
template <int CIN, int COUT>
__device__ __forceinline__ unsigned int ldcvt(const float* __restrict__ xA, int CA,
                                              const float* __restrict__ xB,
                                              int reluA, int r, int c) {
    float2 v;
    if (c < CA) {
        v = __ldg(reinterpret_cast<const float2*>(xA + (size_t)r * CA + c));
        if (reluA) { v.x = fmaxf(v.x, 0.f); v.y = fmaxf(v.y, 0.f); }
    } else {
        v = __ldg(reinterpret_cast<const float2*>(xB + (size_t)r * (CIN - CA) + (c - CA)));
    }
    __half2 h = __floats2half2_rn(v.x, v.y);
    return *reinterpret_cast<unsigned int*>(&h);
}

template <int CIN, int COUT>
__global__ void __launch_bounds__(256)
node_mma_kernel(const float* __restrict__ xA, int CA,
                const float* __restrict__ xB,
                const int* __restrict__ gidx, int reluA,
                const unsigned int* __restrict__ Bp,
                const float* __restrict__ bias,
                __half* __restrict__ Z, float* __restrict__ O) {
    constexpr int KS = CIN / 16;
    constexpr int NT_TOT = 10 * COUT / 8;
    constexpr int NTW = NT_TOT / 4;
    constexpr int ZW = 9 * COUT;

    int tid = threadIdx.x;
    int lane = tid & 31;
    int wid = tid >> 5;
    int mg = wid >> 2;
    int ng = wid & 3;
    int g = lane >> 2;
    int tig = lane & 3;
    int nodeBase = blockIdx.x * 32;

    int n0 = nodeBase + mg * 16 + g;
    int n1 = n0 + 8;
    int r0 = gidx ? __ldg(gidx + n0) : n0;
    int r1 = gidx ? __ldg(gidx + n1) : n1;

    float acc[NTW][4];
#pragma unroll
    for (int t = 0; t < NTW; t++)
#pragma unroll
        for (int q = 0; q < 4; q++) acc[t][q] = 0.f;

#pragma unroll
    for (int ks = 0; ks < KS; ks++) {
        int cb = ks * 16 + tig * 2;
        unsigned int a0 = ldcvt<CIN, COUT>(xA, CA, xB, reluA, r0, cb);
        unsigned int a1 = ldcvt<CIN, COUT>(xA, CA, xB, reluA, r1, cb);
        unsigned int a2 = ldcvt<CIN, COUT>(xA, CA, xB, reluA, r0, cb + 8);
        unsigned int a3 = ldcvt<CIN, COUT>(xA, CA, xB, reluA, r1, cb + 8);
#pragma unroll
        for (int nt = 0; nt < NTW; nt++) {
            int gnt = ng * NTW + nt;
            uint2 bb = __ldg(reinterpret_cast<const uint2*>(
                &Bp[((gnt * KS + ks) * 32 + lane) * 2]));
            asm volatile(
                "mma.sync.aligned.m16n8k16.row.col.f32.f16.f16.f32 "
                "{%0,%1,%2,%3}, {%4,%5,%6,%7}, {%8,%9}, {%0,%1,%2,%3};"
                : "+f"(acc[nt][0]), "+f"(acc[nt][1]),
                  "+f"(acc[nt][2]), "+f"(acc[nt][3])
                : "r"(a0), "r"(a1), "r"(a2), "r"(a3), "r"(bb.x), "r"(bb.y));
        }
    }

#pragma unroll
    for (int nt = 0; nt < NTW; nt++) {
        int gnt = ng * NTW + nt;
        int jbase = gnt * 8 + tig * 2;
        if (gnt * 8 < ZW) {
            __half2 h0 = __floats2half2_rn(acc[nt][0], acc[nt][1]);
            __half2 h1 = __floats2half2_rn(acc[nt][2], acc[nt][3]);
            *reinterpret_cast<__half2*>(Z + (size_t)n0 * ZW + jbase) = h0;
            *reinterpret_cast<__half2*>(Z + (size_t)n1 * ZW + jbase) = h1;
        } else {
            int co = jbase - ZW;
            float bx = __ldg(bias + co), by = __ldg(bias + co + 1);
            float2 w0 = make_float2(acc[nt][0] + bx, acc[nt][1] + by);
            float2 w1 = make_float2(acc[nt][2] + bx, acc[nt][3] + by);
            *reinterpret_cast<float2*>(O + (size_t)n0 * COUT + co) = w0;
            *reinterpret_cast<float2*>(O + (size_t)n1 * COUT + co) = w1;
        }
    }
}

// ---------------------------------------------------------------------------
// Edge kernel (8 ch/thread) on src-sorted permuted edge arrays.
// ---------------------------------------------------------------------------
template <int COUT>
__global__ void edge_kernel(const int* __restrict__ src,
                            const int* __restrict__ dst,
                            const float2* __restrict__ ps,
                            const __half* __restrict__ Z,
                            float* __restrict__ O, int E) {
    constexpr int TPE = COUT / 8;
    int tid = blockIdx.x * blockDim.x + threadIdx.x;
    int e = tid / TPE;
    int g = tid - e * TPE;
    if (e >= E) return;

    float2 p = __ldg(ps + e);
    float t0 = p.x, t1 = p.y;
    float a0 = 0.5f * (1.f - t0) * (1.f - t0);
    float a1 = -t0 * t0 + t0 + 0.5f;
    float a2 = 0.5f * t0 * t0;
    float c0 = 0.5f * (1.f - t1) * (1.f - t1);
    float c1 = -t1 * t1 + t1 + 0.5f;
    float c2 = 0.5f * t1 * t1;
    float b[9] = {a0 * c0, a0 * c1, a0 * c2,
                  a1 * c0, a1 * c1, a1 * c2,
                  a2 * c0, a2 * c1, a2 * c2};

    int s = __ldg(src + e);
    int d = __ldg(dst + e);
    const __half* zb = Z + (size_t)s * (9 * COUT) + g * 8;
    float4 acc0 = make_float4(0.f, 0.f, 0.f, 0.f);
    float4 acc1 = make_float4(0.f, 0.f, 0.f, 0.f);
#pragma unroll
    for (int k = 0; k < 9; k++) {
        float bk = b[k];
        uint4 raw = __ldg(reinterpret_cast<const uint4*>(zb + k * COUT));
        float2 f0 = __half22float2(*reinterpret_cast<const __half2*>(&raw.x));
        float2 f1 = __half22float2(*reinterpret_cast<const __half2*>(&raw.y));
        float2 f2 = __half22float2(*reinterpret_cast<const __half2*>(&raw.z));
        float2 f3 = __half22float2(*reinterpret_cast<const __half2*>(&raw.w));
        acc0.x = fmaf(bk, f0.x, acc0.x);
        acc0.y = fmaf(bk, f0.y, acc0.y);
        acc0.z = fmaf(bk, f1.x, acc0.z);
        acc0.w = fmaf(bk, f1.y, acc0.w);
        acc1.x = fmaf(bk, f2.x, acc1.x);
        acc1.y = fmaf(bk, f2.y, acc1.y);
        acc1.z = fmaf(bk, f3.x, acc1.z);
        acc1.w = fmaf(bk, f3.y, acc1.w);
    }
    float* o = O + (size_t)d * COUT + g * 8;
    asm volatile("red.global.add.v4.f32 [%0], {%1, %2, %3, %4};"
                 :: "l"(o), "f"(acc0.x), "f"(acc0.y), "f"(acc0.z), "f"(acc0.w)
                 : "memory");
    asm volatile("red.global.add.v4.f32 [%0], {%1, %2, %3, %4};"
                 :: "l"(o + 4), "f"(acc1.x), "f"(acc1.y), "f"(acc1.z), "f"(acc1.w)
                 : "memory");
}

__global__ void relu_copy4_kernel(const float4* __restrict__ in,
                                  float4* __restrict__ out, int n4) {
    int i = blockIdx.x * blockDim.x + threadIdx.x;
    if (i >= n4) return;
    float4 v = in[i];
    v.x = fmaxf(v.x, 0.f); v.y = fmaxf(v.y, 0.f);
    v.z = fmaxf(v.z, 0.f); v.w = fmaxf(v.w, 0.f);
    out[i] = v;
}

// ---------------------------------------------------------------------------
extern "C" void kernel_launch(void* const* d_in, const int* in_sizes, int n_in,
                              void* d_out, int out_size) {
    const float* x0      = (const float*)d_in[0];
    const int*   unpool1 = (const int*)d_in[1];
    const int*   edge1   = (const int*)d_in[2];
    const float* pseudo1 = (const float*)d_in[3];
    const float* skip1   = (const float*)d_in[4];
    const int*   unpool2 = (const int*)d_in[5];
    const int*   edge2   = (const int*)d_in[6];
    const float* pseudo2 = (const float*)d_in[7];
    const float* skip2   = (const float*)d_in[8];
    const float* W1a = (const float*)d_in[9];
    const float* R1a = (const float*)d_in[10];
    const float* b1a = (const float*)d_in[11];
    const float* W2a = (const float*)d_in[12];
    const float* R2a = (const float*)d_in[13];
    const float* b2a = (const float*)d_in[14];
    const float* W1b = (const float*)d_in[15];
    const float* R1b = (const float*)d_in[16];
    const float* b1b = (const float*)d_in[17];
    const float* W2b = (const float*)d_in[18];
    const float* R2b = (const float*)d_in[19];
    const float* b2b = (const float*)d_in[20];

    __half* ZP;
    float *bufA, *bufB;
    unsigned int* Bp;
    int *offs, *bsum, *srcP, *dstP;
    float2* psP;
    cudaGetSymbolAddress((void**)&ZP, g_Z);
    cudaGetSymbolAddress((void**)&bufA, g_bufA);
    cudaGetSymbolAddress((void**)&bufB, g_bufB);
    cudaGetSymbolAddress((void**)&Bp, g_Bp);
    cudaGetSymbolAddress((void**)&offs, g_offs);
    cudaGetSymbolAddress((void**)&bsum, g_bsum);
    cudaGetSymbolAddress((void**)&srcP, g_srcP);
    cudaGetSymbolAddress((void**)&dstP, g_dstP);
    cudaGetSymbolAddress((void**)&psP, g_psP);

    const int N1 = N1C, N2 = N2C, E1 = E1C, E2 = E2C;

    // ---- pack B fragments ----
    pack_all_kernel<<<(19200 + 255) / 256, 256>>>(W1a, R1a, W2a, R2a,
                                                  W1b, R1b, W2b, R2b, Bp);

    // ---- counting sort of all edges by src (both levels together) ----
    zero_kernel<<<(NKEYS + 255) / 256, 256>>>(offs, NKEYS);
    hist_kernel<<<(NEDGE + 255) / 256, 256>>>(edge1, edge2, offs);
    scan1_kernel<<<NB1, 1024>>>(offs, bsum);
    scan2_kernel<<<1, 64>>>(bsum);
    scatter_kernel<<<(NEDGE + 255) / 256, 256>>>(edge1, edge1 + E1, pseudo1,
                                                 edge2, edge2 + E2, pseudo2,
                                                 offs, bsum, srcP, dstP, psP);

    // ===================== Level 1: 64 -> 32 (N1, E1) =====================
    node_mma_kernel<64, 32><<<N1 / 32, 256>>>(x0, 64, nullptr, unpool1, 0,
                                              Bp + BP_1A, b1a, ZP, bufA);
    edge_kernel<32><<<(E1 * 4 + 255) / 256, 256>>>(srcP, dstP, psP, ZP, bufA, E1);

    node_mma_kernel<64, 32><<<N1 / 32, 256>>>(bufA, 32, skip1, nullptr, 1,
                                              Bp + BP_1A, b1a, ZP, bufB);
    edge_kernel<32><<<(E1 * 4 + 255) / 256, 256>>>(srcP, dstP, psP, ZP, bufB, E1);

    node_mma_kernel<32, 32><<<N1 / 32, 256>>>(bufB, 32, nullptr, nullptr, 1,
                                              Bp + BP_2A, b2a, ZP, bufA);
    edge_kernel<32><<<(E1 * 4 + 255) / 256, 256>>>(srcP, dstP, psP, ZP, bufA, E1);
    // bufA = h1 (pre-relu; relu applied at gather below)

    // ===================== Level 2: 32 -> 16 (N2, E2) =====================
    node_mma_kernel<32, 16><<<N2 / 32, 256>>>(bufA, 32, nullptr, unpool2, 1,
                                              Bp + BP_1B, b1b, ZP, bufB);
    edge_kernel<16><<<(E2 * 2 + 255) / 256, 256>>>(srcP + E1, dstP + E1, psP + E1, ZP, bufB, E2);

    node_mma_kernel<32, 16><<<N2 / 32, 256>>>(bufB, 16, skip2, nullptr, 1,
                                              Bp + BP_1B, b1b, ZP, bufA);
    edge_kernel<16><<<(E2 * 2 + 255) / 256, 256>>>(srcP + E1, dstP + E1, psP + E1, ZP, bufA, E2);

    node_mma_kernel<16, 16><<<N2 / 32, 256>>>(bufA, 16, nullptr, nullptr, 1,
                                              Bp + BP_2B, b2b, ZP, bufB);
    edge_kernel<16><<<(E2 * 2 + 255) / 256, 256>>>(srcP + E1, dstP + E1, psP + E1, ZP, bufB, E2);

    // final relu -> output
    int n4 = N2 * 16 / 4;
    relu_copy4_kernel<<<(n4 + 255) / 256, 256>>>((const float4*)bufB,
                                                 (float4*)d_out, n4);
}

// round 16
// speedup vs baseline: 1.0558x; 1.0118x over previous
#include <cuda_runtime.h>
#include <cuda_fp16.h>
#include <cstdint>

// Problem constants (fixed by the dataset)
#define N0C 10000
#define N1C 40000
#define N2C 160000
#define E1C 240000
#define E2C 960000
#define NKEYS (N1C + N2C)          // 200000 (concatenated src-key domain)
#define NEDGE (E1C + E2C)          // 1200000
#define NB1 ((NKEYS + 4095) / 4096) // 49 scan blocks

// Static scratch (no allocation allowed)
__device__ __half g_Z[N2C * 9 * 16];               // 46.1 MB (>= N1C*9*32 halves)
__device__ float g_bufA[N2C * 32];                 // 20.5 MB
__device__ float g_bufB[N2C * 32];                 // 20.5 MB
__device__ unsigned int g_Bp[19200];               // packed B fragments
__device__ int g_offs[NKEYS];
__device__ int g_bsum[64];
__device__ int g_srcP[NEDGE];
__device__ int g_dstP[NEDGE];
__device__ float2 g_psP[NEDGE];

#define BP_1A 0
#define BP_2A 10240
#define BP_1B 15360
#define BP_2B 17920

// ===========================================================================
// Pack B fragments (mma.m16n8k16 fragment order)
// ===========================================================================
__device__ __forceinline__ float wt_val(const float* __restrict__ W,
                                        const float* __restrict__ R,
                                        int CIN, int COUT, int j, int k) {
    if (j < 9 * COUT) {
        int kk = j / COUT;
        int co = j - kk * COUT;
        return W[((size_t)kk * CIN + k) * COUT + co];
    }
    return R[(size_t)k * COUT + (j - 9 * COUT)];
}

__device__ __forceinline__ void pack_b_one(const float* __restrict__ W,
                                           const float* __restrict__ R,
                                           int CIN, int COUT,
                                           unsigned int* __restrict__ Bp, int u) {
    int r = u & 1;
    int lane = (u >> 1) & 31;
    int rest = u >> 6;
    int KS = CIN / 16;
    int ks = rest % KS;
    int nt = rest / KS;
    int j = nt * 8 + (lane >> 2);
    int kb = ks * 16 + (lane & 3) * 2 + r * 8;
    __half2 h = __floats2half2_rn(wt_val(W, R, CIN, COUT, j, kb),
                                  wt_val(W, R, CIN, COUT, j, kb + 1));
    Bp[u] = *reinterpret_cast<unsigned int*>(&h);
}

__global__ void pack_all_kernel(const float* W1a, const float* R1a,
                                const float* W2a, const float* R2a,
                                const float* W1b, const float* R1b,
                                const float* W2b, const float* R2b,
                                unsigned int* __restrict__ Bp) {
    int i = blockIdx.x * blockDim.x + threadIdx.x;
    if (i < 10240)       pack_b_one(W1a, R1a, 64, 32, Bp + BP_1A, i);
    else if (i < 15360)  pack_b_one(W2a, R2a, 32, 32, Bp + BP_2A, i - 10240);
    else if (i < 17920)  pack_b_one(W1b, R1b, 32, 16, Bp + BP_1B, i - 15360);
    else if (i < 19200)  pack_b_one(W2b, R2b, 16, 16, Bp + BP_2B, i - 17920);
}

// ===========================================================================
// Counting sort of ALL edges (both levels) by src key.
// ===========================================================================
__global__ void zero_kernel(int* __restrict__ p, int n) {
    int i = blockIdx.x * blockDim.x + threadIdx.x;
    if (i < n) p[i] = 0;
}

__global__ void hist_kernel(const int* __restrict__ e1src,
                            const int* __restrict__ e2src,
                            int* __restrict__ cnt) {
    int i = blockIdx.x * blockDim.x + threadIdx.x;
    if (i >= NEDGE) return;
    int key = (i < E1C) ? __ldg(e1src + i) : (N1C + __ldg(e2src + (i - E1C)));
    atomicAdd(&cnt[key], 1);
}

// Block scan: 1024 threads x 4 elems = 4096/block; warp-shuffle based.
__global__ void scan1_kernel(int* __restrict__ offs, int* __restrict__ bsum) {
    __shared__ int wsum[32];
    int t = threadIdx.x;
    int lane = t & 31;
    int w = t >> 5;
    int base = blockIdx.x * 4096 + t * 4;
    int c0 = (base + 0 < NKEYS) ? offs[base + 0] : 0;
    int c1 = (base + 1 < NKEYS) ? offs[base + 1] : 0;
    int c2 = (base + 2 < NKEYS) ? offs[base + 2] : 0;
    int c3 = (base + 3 < NKEYS) ? offs[base + 3] : 0;
    int s = c0 + c1 + c2 + c3;
    int v = s;
#pragma unroll
    for (int off = 1; off < 32; off <<= 1) {
        int u = __shfl_up_sync(0xFFFFFFFFu, v, off);
        if (lane >= off) v += u;
    }
    if (lane == 31) wsum[w] = v;
    __syncthreads();
    if (w == 0) {
        int x = wsum[lane];
        int y = x;
#pragma unroll
        for (int off = 1; off < 32; off <<= 1) {
            int u = __shfl_up_sync(0xFFFFFFFFu, y, off);
            if (lane >= off) y += u;
        }
        wsum[lane] = y - x;     // exclusive warp offsets
    }
    __syncthreads();
    int incl = v + wsum[w];     // inclusive over block
    int excl = incl - s;
    if (t == 1023) bsum[blockIdx.x] = incl;
    if (base + 0 < NKEYS) offs[base + 0] = excl;
    if (base + 1 < NKEYS) offs[base + 1] = excl + c0;
    if (base + 2 < NKEYS) offs[base + 2] = excl + c0 + c1;
    if (base + 3 < NKEYS) offs[base + 3] = excl + c0 + c1 + c2;
}

__global__ void scan2_kernel(int* __restrict__ bsum) {
    int t = threadIdx.x;       // 64 threads, NB1 <= 64
    int v = (t < NB1) ? bsum[t] : 0;
    __shared__ int sh[64];
    sh[t] = v;
    __syncthreads();
    for (int off = 1; off < 64; off <<= 1) {
        int u = (t >= off) ? sh[t - off] : 0;
        __syncthreads();
        sh[t] += u;
        __syncthreads();
    }
    if (t < NB1) bsum[t] = sh[t] - v;   // exclusive
}

// Scatter with block-offset add folded in: pos = local-scan + bsum[blk].
__global__ void scatter_kernel(const int* __restrict__ e1src, const int* __restrict__ e1dst,
                               const float* __restrict__ ps1,
                               const int* __restrict__ e2src, const int* __restrict__ e2dst,
                               const float* __restrict__ ps2,
                               int* __restrict__ offs, const int* __restrict__ bsum,
                               int* __restrict__ srcP, int* __restrict__ dstP,
                               float2* __restrict__ psP) {
    int i = blockIdx.x * blockDim.x + threadIdx.x;
    if (i >= NEDGE) return;
    int s, d, key; float2 ps;
    if (i < E1C) {
        s = __ldg(e1src + i); d = __ldg(e1dst + i);
        ps = __ldg(reinterpret_cast<const float2*>(ps1) + i);
        key = s;
    } else {
        int j = i - E1C;
        s = __ldg(e2src + j); d = __ldg(e2dst + j);
        ps = __ldg(reinterpret_cast<const float2*>(ps2) + j);
        key = N1C + s;
    }
    int pos = atomicAdd(&offs[key], 1) + __ldg(&bsum[key >> 12]);
    srcP[pos] = s; dstP[pos] = d; psP[pos] = ps;
}

// ===========================================================================
// Warp-autonomous HMMA node kernel (R8/R13 shape): NO smem, NO barriers,
// plain launch_bounds(256) -> natural 80 regs, 3 blocks/SM.
// ===========================================================================
template <int CIN, int COUT>
__device__ __forceinline__ unsigned int ldcvt(const float* __restrict__ xA, int CA,
                                              const float* __restrict__ xB,
                                              int reluA, int r, int c) {
    float2 v;
    if (c < CA) {
        v = __ldg(reinterpret_cast<const float2*>(xA + (size_t)r * CA + c));
        if (reluA) { v.x = fmaxf(v.x, 0.f); v.y = fmaxf(v.y, 0.f); }
    } else {
        v = __ldg(reinterpret_cast<const float2*>(xB + (size_t)r * (CIN - CA) + (c - CA)));
    }
    __half2 h = __floats2half2_rn(v.x, v.y);
    return *reinterpret_cast<unsigned int*>(&h);
}

template <int CIN, int COUT>
__global__ void __launch_bounds__(256)
node_mma_kernel(const float* __restrict__ xA, int CA,
                const float* __restrict__ xB,
                const int* __restrict__ gidx, int reluA,
                const unsigned int* __restrict__ Bp,
                const float* __restrict__ bias,
                __half* __restrict__ Z, float* __restrict__ O) {
    constexpr int KS = CIN / 16;
    constexpr int NT_TOT = 10 * COUT / 8;
    constexpr int NTW = NT_TOT / 4;
    constexpr int ZW = 9 * COUT;

    int tid = threadIdx.x;
    int lane = tid & 31;
    int wid = tid >> 5;
    int mg = wid >> 2;
    int ng = wid & 3;
    int g = lane >> 2;
    int tig = lane & 3;
    int nodeBase = blockIdx.x * 32;

    int n0 = nodeBase + mg * 16 + g;
    int n1 = n0 + 8;
    int r0 = gidx ? __ldg(gidx + n0) : n0;
    int r1 = gidx ? __ldg(gidx + n1) : n1;

    float acc[NTW][4];
#pragma unroll
    for (int t = 0; t < NTW; t++)
#pragma unroll
        for (int q = 0; q < 4; q++) acc[t][q] = 0.f;

#pragma unroll
    for (int ks = 0; ks < KS; ks++) {
        int cb = ks * 16 + tig * 2;
        unsigned int a0 = ldcvt<CIN, COUT>(xA, CA, xB, reluA, r0, cb);
        unsigned int a1 = ldcvt<CIN, COUT>(xA, CA, xB, reluA, r1, cb);
        unsigned int a2 = ldcvt<CIN, COUT>(xA, CA, xB, reluA, r0, cb + 8);
        unsigned int a3 = ldcvt<CIN, COUT>(xA, CA, xB, reluA, r1, cb + 8);
#pragma unroll
        for (int nt = 0; nt < NTW; nt++) {
            int gnt = ng * NTW + nt;
            uint2 bb = __ldg(reinterpret_cast<const uint2*>(
                &Bp[((gnt * KS + ks) * 32 + lane) * 2]));
            asm volatile(
                "mma.sync.aligned.m16n8k16.row.col.f32.f16.f16.f32 "
                "{%0,%1,%2,%3}, {%4,%5,%6,%7}, {%8,%9}, {%0,%1,%2,%3};"
                : "+f"(acc[nt][0]), "+f"(acc[nt][1]),
                  "+f"(acc[nt][2]), "+f"(acc[nt][3])
                : "r"(a0), "r"(a1), "r"(a2), "r"(a3), "r"(bb.x), "r"(bb.y));
        }
    }

#pragma unroll
    for (int nt = 0; nt < NTW; nt++) {
        int gnt = ng * NTW + nt;
        int jbase = gnt * 8 + tig * 2;
        if (gnt * 8 < ZW) {
            __half2 h0 = __floats2half2_rn(acc[nt][0], acc[nt][1]);
            __half2 h1 = __floats2half2_rn(acc[nt][2], acc[nt][3]);
            *reinterpret_cast<__half2*>(Z + (size_t)n0 * ZW + jbase) = h0;
            *reinterpret_cast<__half2*>(Z + (size_t)n1 * ZW + jbase) = h1;
        } else {
            int co = jbase - ZW;
            float bx = __ldg(bias + co), by = __ldg(bias + co + 1);
            float2 w0 = make_float2(acc[nt][0] + bx, acc[nt][1] + by);
            float2 w1 = make_float2(acc[nt][2] + bx, acc[nt][3] + by);
            *reinterpret_cast<float2*>(O + (size_t)n0 * COUT + co) = w0;
            *reinterpret_cast<float2*>(O + (size_t)n1 * COUT + co) = w1;
        }
    }
}

// ---------------------------------------------------------------------------
// Edge kernel (8 ch/thread) on src-sorted permuted edge arrays.
// ---------------------------------------------------------------------------
template <int COUT>
__global__ void edge_kernel(const int* __restrict__ src,
                            const int* __restrict__ dst,
                            const float2* __restrict__ ps,
                            const __half* __restrict__ Z,
                            float* __restrict__ O, int E) {
    constexpr int TPE = COUT / 8;
    int tid = blockIdx.x * blockDim.x + threadIdx.x;
    int e = tid / TPE;
    int g = tid - e * TPE;
    if (e >= E) return;

    float2 p = __ldg(ps + e);
    float t0 = p.x, t1 = p.y;
    float a0 = 0.5f * (1.f - t0) * (1.f - t0);
    float a1 = -t0 * t0 + t0 + 0.5f;
    float a2 = 0.5f * t0 * t0;
    float c0 = 0.5f * (1.f - t1) * (1.f - t1);
    float c1 = -t1 * t1 + t1 + 0.5f;
    float c2 = 0.5f * t1 * t1;
    float b[9] = {a0 * c0, a0 * c1, a0 * c2,
                  a1 * c0, a1 * c1, a1 * c2,
                  a2 * c0, a2 * c1, a2 * c2};

    int s = __ldg(src + e);
    int d = __ldg(dst + e);
    const __half* zb = Z + (size_t)s * (9 * COUT) + g * 8;
    float4 acc0 = make_float4(0.f, 0.f, 0.f, 0.f);
    float4 acc1 = make_float4(0.f, 0.f, 0.f, 0.f);
#pragma unroll
    for (int k = 0; k < 9; k++) {
        float bk = b[k];
        uint4 raw = __ldg(reinterpret_cast<const uint4*>(zb + k * COUT));
        float2 f0 = __half22float2(*reinterpret_cast<const __half2*>(&raw.x));
        float2 f1 = __half22float2(*reinterpret_cast<const __half2*>(&raw.y));
        float2 f2 = __half22float2(*reinterpret_cast<const __half2*>(&raw.z));
        float2 f3 = __half22float2(*reinterpret_cast<const __half2*>(&raw.w));
        acc0.x = fmaf(bk, f0.x, acc0.x);
        acc0.y = fmaf(bk, f0.y, acc0.y);
        acc0.z = fmaf(bk, f1.x, acc0.z);
        acc0.w = fmaf(bk, f1.y, acc0.w);
        acc1.x = fmaf(bk, f2.x, acc1.x);
        acc1.y = fmaf(bk, f2.y, acc1.y);
        acc1.z = fmaf(bk, f3.x, acc1.z);
        acc1.w = fmaf(bk, f3.y, acc1.w);
    }
    float* o = O + (size_t)d * COUT + g * 8;
    asm volatile("red.global.add.v4.f32 [%0], {%1, %2, %3, %4};"
                 :: "l"(o), "f"(acc0.x), "f"(acc0.y), "f"(acc0.z), "f"(acc0.w)
                 : "memory");
    asm volatile("red.global.add.v4.f32 [%0], {%1, %2, %3, %4};"
                 :: "l"(o + 4), "f"(acc1.x), "f"(acc1.y), "f"(acc1.z), "f"(acc1.w)
                 : "memory");
}

__global__ void relu_copy4_kernel(const float4* __restrict__ in,
                                  float4* __restrict__ out, int n4) {
    int i = blockIdx.x * blockDim.x + threadIdx.x;
    if (i >= n4) return;
    float4 v = in[i];
    v.x = fmaxf(v.x, 0.f); v.y = fmaxf(v.y, 0.f);
    v.z = fmaxf(v.z, 0.f); v.w = fmaxf(v.w, 0.f);
    out[i] = v;
}

// ---------------------------------------------------------------------------
extern "C" void kernel_launch(void* const* d_in, const int* in_sizes, int n_in,
                              void* d_out, int out_size) {
    const float* x0      = (const float*)d_in[0];
    const int*   unpool1 = (const int*)d_in[1];
    const int*   edge1   = (const int*)d_in[2];
    const float* pseudo1 = (const float*)d_in[3];
    const float* skip1   = (const float*)d_in[4];
    const int*   unpool2 = (const int*)d_in[5];
    const int*   edge2   = (const int*)d_in[6];
    const float* pseudo2 = (const float*)d_in[7];
    const float* skip2   = (const float*)d_in[8];
    const float* W1a = (const float*)d_in[9];
    const float* R1a = (const float*)d_in[10];
    const float* b1a = (const float*)d_in[11];
    const float* W2a = (const float*)d_in[12];
    const float* R2a = (const float*)d_in[13];
    const float* b2a = (const float*)d_in[14];
    const float* W1b = (const float*)d_in[15];
    const float* R1b = (const float*)d_in[16];
    const float* b1b = (const float*)d_in[17];
    const float* W2b = (const float*)d_in[18];
    const float* R2b = (const float*)d_in[19];
    const float* b2b = (const float*)d_in[20];

    __half* ZP;
    float *bufA, *bufB;
    unsigned int* Bp;
    int *offs, *bsum, *srcP, *dstP;
    float2* psP;
    cudaGetSymbolAddress((void**)&ZP, g_Z);
    cudaGetSymbolAddress((void**)&bufA, g_bufA);
    cudaGetSymbolAddress((void**)&bufB, g_bufB);
    cudaGetSymbolAddress((void**)&Bp, g_Bp);
    cudaGetSymbolAddress((void**)&offs, g_offs);
    cudaGetSymbolAddress((void**)&bsum, g_bsum);
    cudaGetSymbolAddress((void**)&srcP, g_srcP);
    cudaGetSymbolAddress((void**)&dstP, g_dstP);
    cudaGetSymbolAddress((void**)&psP, g_psP);

    const int N1 = N1C, N2 = N2C, E1 = E1C, E2 = E2C;

    // ---- fork a side stream for the sort chain (captured as parallel graph
    //      branch). CPU-side creation happens only at capture time; streams
    //      and events are intentionally leaked (destroying mid-capture is
    //      not allowed, and kernel_launch is only called a handful of times).
    cudaStream_t s2;
    cudaStreamCreateWithFlags(&s2, cudaStreamNonBlocking);
    cudaEvent_t evFork, evJoin;
    cudaEventCreateWithFlags(&evFork, cudaEventDisableTiming);
    cudaEventCreateWithFlags(&evJoin, cudaEventDisableTiming);

    cudaEventRecord(evFork, 0);
    cudaStreamWaitEvent(s2, evFork, 0);

    // ---- sort chain on side stream ----
    zero_kernel<<<(NKEYS + 255) / 256, 256, 0, s2>>>(offs, NKEYS);
    hist_kernel<<<(NEDGE + 255) / 256, 256, 0, s2>>>(edge1, edge2, offs);
    scan1_kernel<<<NB1, 1024, 0, s2>>>(offs, bsum);
    scan2_kernel<<<1, 64, 0, s2>>>(bsum);
    scatter_kernel<<<(NEDGE + 255) / 256, 256, 0, s2>>>(edge1, edge1 + E1, pseudo1,
                                                        edge2, edge2 + E2, pseudo2,
                                                        offs, bsum, srcP, dstP, psP);
    cudaEventRecord(evJoin, s2);

    // ---- main stream: pack + level-1 conv1 node kernel (independent) ----
    pack_all_kernel<<<(19200 + 255) / 256, 256>>>(W1a, R1a, W2a, R2a,
                                                  W1b, R1b, W2b, R2b, Bp);
    node_mma_kernel<64, 32><<<N1 / 32, 256>>>(x0, 64, nullptr, unpool1, 0,
                                              Bp + BP_1A, b1a, ZP, bufA);

    // ---- join: first edge pass needs the permuted edge arrays ----
    cudaStreamWaitEvent(0, evJoin, 0);

    // ===================== Level 1: 64 -> 32 (N1, E1) =====================
    edge_kernel<32><<<(E1 * 4 + 255) / 256, 256>>>(srcP, dstP, psP, ZP, bufA, E1);

    node_mma_kernel<64, 32><<<N1 / 32, 256>>>(bufA, 32, skip1, nullptr, 1,
                                              Bp + BP_1A, b1a, ZP, bufB);
    edge_kernel<32><<<(E1 * 4 + 255) / 256, 256>>>(srcP, dstP, psP, ZP, bufB, E1);

    node_mma_kernel<32, 32><<<N1 / 32, 256>>>(bufB, 32, nullptr, nullptr, 1,
                                              Bp + BP_2A, b2a, ZP, bufA);
    edge_kernel<32><<<(E1 * 4 + 255) / 256, 256>>>(srcP, dstP, psP, ZP, bufA, E1);
    // bufA = h1 (pre-relu; relu applied at gather below)

    // ===================== Level 2: 32 -> 16 (N2, E2) =====================
    node_mma_kernel<32, 16><<<N2 / 32, 256>>>(bufA, 32, nullptr, unpool2, 1,
                                              Bp + BP_1B, b1b, ZP, bufB);
    edge_kernel<16><<<(E2 * 2 + 255) / 256, 256>>>(srcP + E1, dstP + E1, psP + E1, ZP, bufB, E2);

    node_mma_kernel<32, 16><<<N2 / 32, 256>>>(bufB, 16, skip2, nullptr, 1,
                                              Bp + BP_1B, b1b, ZP, bufA);
    edge_kernel<16><<<(E2 * 2 + 255) / 256, 256>>>(srcP + E1, dstP + E1, psP + E1, ZP, bufA, E2);

    node_mma_kernel<16, 16><<<N2 / 32, 256>>>(bufA, 16, nullptr, nullptr, 1,
                                              Bp + BP_2B, b2b, ZP, bufB);
    edge_kernel<16><<<(E2 * 2 + 255) / 256, 256>>>(srcP + E1, dstP + E1, psP + E1, ZP, bufB, E2);

    // final relu -> output
    int n4 = N2 * 16 / 4;
    relu_copy4_kernel<<<(n4 + 255) / 256, 256>>>((const float4*)bufB,
                                                 (float4*)d_out, n4);
}